// round 7
// baseline (speedup 1.0000x reference)
#include <cuda_runtime.h>
#include <cuda_fp16.h>

#define BB 2
#define CC 32
#define HH 128
#define WW 416
#define DD 48
#define HW_ (HH*WW)
#define CHW_ (CC*HH*WW)
#define ISCALE 0.05892556509887896f  // 1/sqrt(C*K2) = 1/sqrt(288)

// Emulate the reference's fp16 cast, stored as float32.
__device__ __forceinline__ float h16(float v) {
    return __half2float(__float2half_rn(v));
}

// Packed f32x2 helpers (Blackwell): one instruction = two fp32 FMAs.
__device__ __forceinline__ unsigned long long pk2(float lo, float hi) {
    unsigned long long r;
    asm("mov.b64 %0, {%1, %2};" : "=l"(r) : "f"(lo), "f"(hi));
    return r;
}
__device__ __forceinline__ float2 upk2(unsigned long long v) {
    float2 r;
    asm("mov.b64 {%0, %1}, %2;" : "=f"(r.x), "=f"(r.y) : "l"(v));
    return r;
}
#define FMA2(acc, a, b) \
    asm("fma.rn.f32x2 %0, %1, %2, %0;" : "+l"(acc) : "l"(a), "l"(b))

// Device-global scratch (allocation forbidden)
__device__ float g_Al[BB*CHW_];     // normalized 3x3 box sum of xl
__device__ float g_Br[BB*CHW_];     // normalized 3x3 box sum of xr
__device__ float g_nli[BB*HW_];     // 1/max(||patch_l||, eps)
__device__ float g_nri[BB*HW_];
__device__ float g_Grow[BB*DD*HW_]; // horizontal 3-tap of G_{2d} per row

// ---------------------------------------------------------------------------
// Kernel 1: pre-normalized box sums + patch norms. Shuffle-based horizontal
// 3-tap; no smem, no barriers.
// ---------------------------------------------------------------------------
__global__ __launch_bounds__(448) void cv_prep_kernel(
    const float* __restrict__ xl, const float* __restrict__ xr)
{
    const int t    = threadIdx.x;
    const int wi   = t >> 5;
    const int lane = t & 31;
    const int h    = blockIdx.x;
    const int b    = blockIdx.y;
    const int img  = blockIdx.z;
    const float* x = img ? xr : xl;
    float* gbox    = img ? g_Br : g_Al;
    float* gn      = img ? g_nri : g_nli;

    const int u = wi*30 + lane - 1;          // -1 .. 419
    const bool vu = (u >= 0) && (u < WW);
    const bool h0 = (h > 0), h1 = (h < HH - 1);
    const float* base = x + b*CHW_ + h*WW + (vu ? u : 0);

    float ssum = 0.f;
    float boxv[CC];
    #pragma unroll
    for (int c = 0; c < CC; c++) {
        float r0 = (vu && h0) ? __ldg(base + c*HW_ - WW) : 0.f;
        float r1 =  vu        ? __ldg(base + c*HW_)      : 0.f;
        float r2 = (vu && h1) ? __ldg(base + c*HW_ + WW) : 0.f;
        float cs = r0 + r1 + r2;
        ssum += r0*r0 + r1*r1 + r2*r2;
        float csl = __shfl_up_sync(0xffffffffu, cs, 1);
        float csr = __shfl_down_sync(0xffffffffu, cs, 1);
        boxv[c] = csl + cs + csr;
    }
    float sql = __shfl_up_sync(0xffffffffu, ssum, 1);
    float sqr = __shfl_down_sync(0xffffffffu, ssum, 1);
    float ni = 1.f / fmaxf(sqrtf(sql + ssum + sqr), 1e-3f);

    if (lane >= 1 && lane <= 30 && u < WW) {
        float* ob = gbox + b*CHW_ + h*WW + u;
        #pragma unroll
        for (int c = 0; c < CC; c++) ob[c*HW_] = boxv[c] * ni;
        gn[b*HW_ + h*WW + u] = ni;
    }
}

// ---------------------------------------------------------------------------
// Kernel 2: Grow = horizontal 3-tap of G_{2d}. fp32-paired float2 smem
// (one LDS.64 = two disparities), packed f32x2 FMA, warp-shuffle 3-tap.
// Dynamic smem: 32*308*8 = 78848 B.
// ---------------------------------------------------------------------------
#define XRW 308   // word k -> {xr[lo+k], xr[lo+k-2]}, lo = u0-96

__global__ __launch_bounds__(224) void cv_g_kernel(
    const float* __restrict__ xl,
    const float* __restrict__ xr)
{
    extern __shared__ float2 s_x2[];   // [CC*XRW]

    const int t    = threadIdx.x;
    const int wi   = t >> 5;
    const int lane = t & 31;
    const int u0   = blockIdx.x * 208;
    const int r    = blockIdx.y;
    const int b    = blockIdx.z;
    const int lo   = u0 - 96;
    const int rbase = b*CHW_ + r*WW;

    for (int i = t; i < CC*77; i += 224) {
        int c = i / 77, q = i % 77;
        int col = lo + 4*q;
        float4 f4 = make_float4(0.f,0.f,0.f,0.f);
        if (col >= 0 && col <= WW-4) f4 = *(const float4*)(xr + rbase + c*HW_ + col);
        float m2 = (col-2 >= 0 && col-2 < WW) ? __ldg(xr + rbase + c*HW_ + col - 2) : 0.f;
        float m1 = (col-1 >= 0 && col-1 < WW) ? __ldg(xr + rbase + c*HW_ + col - 1) : 0.f;
        float2* dst = s_x2 + c*XRW + 4*q;
        dst[0] = make_float2(f4.x, m2);
        dst[1] = make_float2(f4.y, m1);
        dst[2] = make_float2(f4.z, f4.x);
        dst[3] = make_float2(f4.w, f4.y);
    }
    __syncthreads();

    const int u = u0 - 1 + wi*30 + lane;     // g column this lane computes
    const bool vu = (u >= 0) && (u < WW);
    unsigned long long rp[CC];
    #pragma unroll
    for (int c = 0; c < CC; c++) {
        float v = vu ? __ldg(xl + rbase + c*HW_ + u) : 0.f;
        rp[c] = pk2(v, v);
    }

    const bool wr = (lane >= 1) && (lane <= 30) && (u <= u0 + 207) && (u < WW);
    const int obase = b*DD*HW_ + r*WW + (wr ? u : 0);

    for (int dp = 0; dp < 24; dp++) {
        const int k = (u - u0) + 96 - 4*dp;  // in [3, 305]
        const unsigned long long* src =
            (const unsigned long long*)(s_x2 + k);
        unsigned long long acc0 = 0ull, acc1 = 0ull;
        #pragma unroll
        for (int c = 0; c < CC; c += 2) {
            FMA2(acc0, src[c*XRW],     rp[c]);
            FMA2(acc1, src[(c+1)*XRW], rp[c+1]);
        }
        float2 a0 = upk2(acc0), a1 = upk2(acc1);
        float g0 = a0.x + a1.x;              // disparity 2dp
        float g1 = a0.y + a1.y;              // disparity 2dp+1
        float s0 = g0 + __shfl_up_sync(0xffffffffu, g0, 1)
                      + __shfl_down_sync(0xffffffffu, g0, 1);
        float s1 = g1 + __shfl_up_sync(0xffffffffu, g1, 1)
                      + __shfl_down_sync(0xffffffffu, g1, 1);
        if (wr) {
            g_Grow[obase + (2*dp)*HW_]   = s0;
            g_Grow[obase + (2*dp+1)*HW_] = s1;
        }
    }
}

// ---------------------------------------------------------------------------
// Kernel 3: LR channel -- vertical 3-tap over Grow + normalization.
// 4 rows per block for ILP.
// ---------------------------------------------------------------------------
__global__ __launch_bounds__(416) void cv_lr_out_kernel(float* __restrict__ out)
{
    const int w  = threadIdx.x;
    const int h0 = blockIdx.x * 4;
    const int d  = blockIdx.y;
    const int b  = blockIdx.z;

    const int ob = (b*3 + 2)*DD*HW_ + d*HW_ + w;
    if (w < d || w >= WW - d) {
        #pragma unroll
        for (int r = 0; r < 4; r++) out[ob + (h0+r)*WW] = 0.f;
        return;
    }
    const int u = w + d;
    const float* gb = g_Grow + (b*DD + d)*HW_ + u;

    float v[6];
    #pragma unroll
    for (int r = 0; r < 6; r++) {
        int row = h0 - 1 + r;
        v[r] = (row >= 0 && row < HH) ? __ldg(gb + row*WW) : 0.f;
    }
    const float* pnl = g_nli + b*HW_ + u;
    const float* pnr = g_nri + b*HW_ + (w - d);
    #pragma unroll
    for (int r = 0; r < 4; r++) {
        int h = h0 + r;
        float s = v[r] + v[r+1] + v[r+2];
        float val = s * __ldg(pnl + h*WW) * __ldg(pnr + h*WW) * ISCALE;
        out[ob + h*WW] = h16(fminf(fmaxf(val, -10.f), 10.f));
    }
}

// ---------------------------------------------------------------------------
// Kernel 4: L and R channels. fp32-paired float2 smem + f32x2 FMA.
// Dynamic smem: 32*(176+180)*8 = 91136 B.
// ---------------------------------------------------------------------------
#define SJ 176   // Al word j -> {A'[u0+j], A'[u0+j+1]}
#define BJ 180   // Br word j -> {B'[lo+j], B'[lo+j-1]}, lo = u0-48

__global__ __launch_bounds__(128) void cv_lrcost_kernel(
    const float* __restrict__ xm, float* __restrict__ out)
{
    extern __shared__ float2 sm2[];
    float2* s_A2 = sm2;             // [CC*SJ]
    float2* s_B2 = sm2 + CC*SJ;     // [CC*BJ]

    const int t  = threadIdx.x;
    const int u0 = blockIdx.x * 128;
    const int h  = blockIdx.y;
    const int b  = blockIdx.z;
    const int grow = b*CHW_ + h*WW;

    for (int i = t; i < CC*44; i += 128) {
        int c = i / 44, q = i % 44;
        int col = u0 + 4*q;
        float4 a4 = make_float4(0.f,0.f,0.f,0.f);
        if (col <= WW-4) a4 = *(const float4*)(g_Al + grow + c*HW_ + col);
        float a5 = (col+4 < WW) ? __ldg(g_Al + grow + c*HW_ + col + 4) : 0.f;
        float2* dst = s_A2 + c*SJ + 4*q;
        dst[0] = make_float2(a4.x, a4.y);
        dst[1] = make_float2(a4.y, a4.z);
        dst[2] = make_float2(a4.z, a4.w);
        dst[3] = make_float2(a4.w, a5);
    }
    for (int i = t; i < CC*45; i += 128) {
        int c = i / 45, q = i % 45;
        int col = u0 - 48 + 4*q;
        float4 b4 = make_float4(0.f,0.f,0.f,0.f);
        if (col >= 0 && col <= WW-4) b4 = *(const float4*)(g_Br + grow + c*HW_ + col);
        float bm1 = (col-1 >= 0 && col-1 < WW) ? __ldg(g_Br + grow + c*HW_ + col - 1) : 0.f;
        float2* dst = s_B2 + c*BJ + 4*q;
        dst[0] = make_float2(b4.x, bm1);
        dst[1] = make_float2(b4.y, b4.x);
        dst[2] = make_float2(b4.z, b4.y);
        dst[3] = make_float2(b4.w, b4.z);
    }
    __syncthreads();

    const int w = u0 + t;
    if (w >= WW) return;

    unsigned long long fp[CC];
    {
        float fv[CC];
        float ss = 0.f;
        const float* pm = xm + b*CHW_ + h*WW + w;
        #pragma unroll
        for (int c = 0; c < CC; c++) {
            float v = __ldg(pm + c*HW_);
            fv[c] = v; ss += v*v;
        }
        float nf = ISCALE / fmaxf(sqrtf(ss), 1e-3f);
        #pragma unroll
        for (int c = 0; c < CC; c++) {
            float v = fv[c] * nf;
            fp[c] = pk2(v, v);
        }
    }

    const int ob = (b*3)*DD*HW_ + h*WW + w;   // channel-L base at d=0
    for (int dp = 0; dp < 24; dp++) {
        const unsigned long long* sa =
            (const unsigned long long*)(s_A2 + (t + 2*dp));        // jA
        const unsigned long long* sb =
            (const unsigned long long*)(s_B2 + (t - 2*dp + 48));   // jB
        unsigned long long aA0 = 0ull, aA1 = 0ull, aB0 = 0ull, aB1 = 0ull;
        #pragma unroll
        for (int c = 0; c < CC; c += 2) {
            FMA2(aA0, sa[c*SJ],     fp[c]);
            FMA2(aA1, sa[(c+1)*SJ], fp[c+1]);
            FMA2(aB0, sb[c*BJ],     fp[c]);
            FMA2(aB1, sb[(c+1)*BJ], fp[c+1]);
        }
        float2 rA0 = upk2(aA0), rA1 = upk2(aA1);
        float2 rB0 = upk2(aB0), rB1 = upk2(aB1);
        float aL0 = rA0.x + rA1.x, aL1 = rA0.y + rA1.y;
        float aR0 = rB0.x + rB1.x, aR1 = rB0.y + rB1.y;
        int o = ob + 2*dp*HW_;
        out[o]              = h16(fminf(fmaxf(aL0, -10.f), 10.f));
        out[o + HW_]        = h16(fminf(fmaxf(aL1, -10.f), 10.f));
        out[o + DD*HW_]     = h16(fminf(fmaxf(aR0, -10.f), 10.f));
        out[o + (DD+1)*HW_] = h16(fminf(fmaxf(aR1, -10.f), 10.f));
    }
}

// ---------------------------------------------------------------------------
extern "C" void kernel_launch(void* const* d_in, const int* in_sizes, int n_in,
                              void* d_out, int out_size)
{
    const float* xl = (const float*)d_in[0];
    const float* xm = (const float*)d_in[1];
    const float* xr = (const float*)d_in[2];
    float* out = (float*)d_out;

    const int smem_g  = CC*XRW*(int)sizeof(float2);        // 78848
    const int smem_lr = CC*(SJ+BJ)*(int)sizeof(float2);    // 91136
    cudaFuncSetAttribute(cv_g_kernel,
        cudaFuncAttributeMaxDynamicSharedMemorySize, smem_g);
    cudaFuncSetAttribute(cv_lrcost_kernel,
        cudaFuncAttributeMaxDynamicSharedMemorySize, smem_lr);

    cv_prep_kernel<<<dim3(HH, BB, 2), 448>>>(xl, xr);
    cv_g_kernel<<<dim3(2, HH, BB), 224, smem_g>>>(xl, xr);
    cv_lr_out_kernel<<<dim3(HH/4, DD, BB), 416>>>(out);
    cv_lrcost_kernel<<<dim3(4, HH, BB), 128, smem_lr>>>(xm, out);
}

// round 8
// speedup vs baseline: 1.0167x; 1.0167x over previous
#include <cuda_runtime.h>
#include <cuda_fp16.h>

#define BB 2
#define CC 32
#define HH 128
#define WW 416
#define DD 48
#define HW_ (HH*WW)
#define CHW_ (CC*HH*WW)
#define ISCALE 0.05892556509887896f  // 1/sqrt(C*K2) = 1/sqrt(288)

// Emulate the reference's fp16 cast, stored as float32.
__device__ __forceinline__ float h16(float v) {
    return __half2float(__float2half_rn(v));
}

// Device-global scratch (allocation forbidden)
__device__ float g_Al[BB*CHW_];     // normalized 3x3 box sum of xl
__device__ float g_Br[BB*CHW_];     // normalized 3x3 box sum of xr
__device__ float g_nli[BB*HW_];     // 1/max(||patch_l||, eps)
__device__ float g_nri[BB*HW_];
__device__ float g_Grow[BB*DD*HW_]; // horizontal 3-tap of G_{2d} per row

// ---------------------------------------------------------------------------
// Kernel 1: pre-normalized box sums + patch norms. Shuffle-based horizontal
// 3-tap; no smem, no barriers.
// ---------------------------------------------------------------------------
__global__ __launch_bounds__(448) void cv_prep_kernel(
    const float* __restrict__ xl, const float* __restrict__ xr)
{
    const int t    = threadIdx.x;
    const int wi   = t >> 5;
    const int lane = t & 31;
    const int h    = blockIdx.x;
    const int b    = blockIdx.y;
    const int img  = blockIdx.z;
    const float* x = img ? xr : xl;
    float* gbox    = img ? g_Br : g_Al;
    float* gn      = img ? g_nri : g_nli;

    const int u = wi*30 + lane - 1;          // -1 .. 419
    const bool vu = (u >= 0) && (u < WW);
    const bool h0 = (h > 0), h1 = (h < HH - 1);
    const float* base = x + b*CHW_ + h*WW + (vu ? u : 0);

    float ssum = 0.f;
    float boxv[CC];
    #pragma unroll
    for (int c = 0; c < CC; c++) {
        float r0 = (vu && h0) ? __ldg(base + c*HW_ - WW) : 0.f;
        float r1 =  vu        ? __ldg(base + c*HW_)      : 0.f;
        float r2 = (vu && h1) ? __ldg(base + c*HW_ + WW) : 0.f;
        float cs = r0 + r1 + r2;
        ssum += r0*r0 + r1*r1 + r2*r2;
        float csl = __shfl_up_sync(0xffffffffu, cs, 1);
        float csr = __shfl_down_sync(0xffffffffu, cs, 1);
        boxv[c] = csl + cs + csr;
    }
    float sql = __shfl_up_sync(0xffffffffu, ssum, 1);
    float sqr = __shfl_down_sync(0xffffffffu, ssum, 1);
    float ni = 1.f / fmaxf(sqrtf(sql + ssum + sqr), 1e-3f);

    if (lane >= 1 && lane <= 30 && u < WW) {
        float* ob = gbox + b*CHW_ + h*WW + u;
        #pragma unroll
        for (int c = 0; c < CC; c++) ob[c*HW_] = boxv[c] * ni;
        gn[b*HW_ + h*WW + u] = ni;
    }
}

// ---------------------------------------------------------------------------
// Kernel 2: Grow = horizontal 3-tap of G_{2d}(r,u) = dot_c(xl[u], xr[u-2d]).
// Scalar fp32 smem (39.4 KB), warp-shuffle 3-tap, no per-d barriers.
// ---------------------------------------------------------------------------
#define XRW 308   // s_xr[k] = xr[lo + k], lo = u0 - 96

__global__ __launch_bounds__(224) void cv_g_kernel(
    const float* __restrict__ xl,
    const float* __restrict__ xr)
{
    __shared__ float s_xr[CC*XRW];

    const int t    = threadIdx.x;
    const int wi   = t >> 5;
    const int lane = t & 31;
    const int u0   = blockIdx.x * 208;
    const int r    = blockIdx.y;
    const int b    = blockIdx.z;
    const int lo   = u0 - 96;
    const int rbase = b*CHW_ + r*WW;

    for (int i = t; i < CC*77; i += 224) {
        int c = i / 77, q = i % 77;
        int col = lo + 4*q;
        float4 v = make_float4(0.f, 0.f, 0.f, 0.f);
        if (col >= 0 && col < WW)
            v = *(const float4*)(xr + rbase + c*HW_ + col);
        *(float4*)&s_xr[c*XRW + 4*q] = v;
    }
    __syncthreads();

    const int u = u0 - 1 + wi*30 + lane;     // g column this lane computes
    const bool vu = (u >= 0) && (u < WW);
    float rl[CC];
    #pragma unroll
    for (int c = 0; c < CC; c++)
        rl[c] = vu ? __ldg(xl + rbase + c*HW_ + u) : 0.f;

    const bool wr = (lane >= 1) && (lane <= 30) && (u <= u0 + 207) && (u < WW);
    const int obase = b*DD*HW_ + r*WW + (wr ? u : 0);

    for (int d = 0; d < DD; d++) {
        const int si = (u - u0) + 96 - 2*d;  // in [1, 306]; zeros where v<0
        float g0 = 0.f, g1 = 0.f;
        #pragma unroll
        for (int c = 0; c < CC; c += 2) {
            g0 += rl[c]   * s_xr[c*XRW + si];
            g1 += rl[c+1] * s_xr[(c+1)*XRW + si];
        }
        float g = g0 + g1;
        float s = g + __shfl_up_sync(0xffffffffu, g, 1)
                    + __shfl_down_sync(0xffffffffu, g, 1);
        if (wr) g_Grow[obase + d*HW_] = s;
    }
}

// ---------------------------------------------------------------------------
// Kernel 3: LR channel -- vertical 3-tap over Grow + normalization.
// 4 rows per block for ILP.
// ---------------------------------------------------------------------------
__global__ __launch_bounds__(416) void cv_lr_out_kernel(float* __restrict__ out)
{
    const int w  = threadIdx.x;
    const int h0 = blockIdx.x * 4;
    const int d  = blockIdx.y;
    const int b  = blockIdx.z;

    const int ob = (b*3 + 2)*DD*HW_ + d*HW_ + w;
    if (w < d || w >= WW - d) {
        #pragma unroll
        for (int r = 0; r < 4; r++) out[ob + (h0+r)*WW] = 0.f;
        return;
    }
    const int u = w + d;
    const float* gb = g_Grow + (b*DD + d)*HW_ + u;

    float v[6];
    #pragma unroll
    for (int r = 0; r < 6; r++) {
        int row = h0 - 1 + r;
        v[r] = (row >= 0 && row < HH) ? __ldg(gb + row*WW) : 0.f;
    }
    const float* pnl = g_nli + b*HW_ + u;
    const float* pnr = g_nri + b*HW_ + (w - d);
    #pragma unroll
    for (int r = 0; r < 4; r++) {
        int h = h0 + r;
        float s = v[r] + v[r+1] + v[r+2];
        float val = s * __ldg(pnl + h*WW) * __ldg(pnr + h*WW) * ISCALE;
        out[ob + h*WW] = h16(fminf(fmaxf(val, -10.f), 10.f));
    }
}

// ---------------------------------------------------------------------------
// Kernel 4: L and R channels. Scalar fp32 smem (45.6 KB), 256 threads:
// warp-group 0 does d 0..23, warp-group 1 does d 24..47 (same 128-w tile).
// Zero-filled halos make all boundary dots naturally zero -> no guards.
// ---------------------------------------------------------------------------
#define SJ 176   // s_A[j] = A'[u0 + j]
#define BJ 180   // s_B[j] = B'[u0 - 48 + j]

__global__ __launch_bounds__(256) void cv_lrcost_kernel(
    const float* __restrict__ xm, float* __restrict__ out)
{
    __shared__ float s_A[CC*SJ];   // 22528 B
    __shared__ float s_B[CC*BJ];   // 23040 B

    const int t  = threadIdx.x;
    const int u0 = blockIdx.x * 128;
    const int h  = blockIdx.y;
    const int b  = blockIdx.z;
    const int grow = b*CHW_ + h*WW;

    for (int i = t; i < CC*44; i += 256) {
        int c = i / 44, q = i % 44;
        int col = u0 + 4*q;                     // multiple of 4
        float4 v = make_float4(0.f, 0.f, 0.f, 0.f);
        if (col < WW) v = *(const float4*)(g_Al + grow + c*HW_ + col);
        *(float4*)&s_A[c*SJ + 4*q] = v;
    }
    for (int i = t; i < CC*45; i += 256) {
        int c = i / 45, q = i % 45;
        int col = u0 - 48 + 4*q;                // multiple of 4
        float4 v = make_float4(0.f, 0.f, 0.f, 0.f);
        if (col >= 0 && col < WW) v = *(const float4*)(g_Br + grow + c*HW_ + col);
        *(float4*)&s_B[c*BJ + 4*q] = v;
    }
    __syncthreads();

    const int tw = t & 127;        // w within tile
    const int d0 = (t >> 7) * 24;  // 0 or 24
    const int w  = u0 + tw;
    if (w >= WW) return;

    float f[CC];
    {
        float ss = 0.f;
        const float* pm = xm + b*CHW_ + h*WW + w;
        #pragma unroll
        for (int c = 0; c < CC; c++) {
            float v = __ldg(pm + c*HW_);
            f[c] = v; ss += v*v;
        }
        float nf = ISCALE / fmaxf(sqrtf(ss), 1e-3f);
        #pragma unroll
        for (int c = 0; c < CC; c++) f[c] *= nf;
    }

    const int ob = (b*3)*DD*HW_ + h*WW + w;   // channel-L base at d=0
    for (int dd = 0; dd < 24; dd++) {
        const int d = d0 + dd;
        const float* sa = s_A + (tw + d);        // jA in [0,174]
        const float* sb = s_B + (tw - d + 48);   // jB in [1,175]
        float aL0 = 0.f, aL1 = 0.f, aR0 = 0.f, aR1 = 0.f;
        #pragma unroll
        for (int c = 0; c < CC; c += 2) {
            aL0 += f[c]   * sa[c*SJ];
            aL1 += f[c+1] * sa[(c+1)*SJ];
            aR0 += f[c]   * sb[c*BJ];
            aR1 += f[c+1] * sb[(c+1)*BJ];
        }
        float aL = aL0 + aL1, aR = aR0 + aR1;
        out[ob + d*HW_]        = h16(fminf(fmaxf(aL, -10.f), 10.f));
        out[ob + (DD + d)*HW_] = h16(fminf(fmaxf(aR, -10.f), 10.f));
    }
}

// ---------------------------------------------------------------------------
extern "C" void kernel_launch(void* const* d_in, const int* in_sizes, int n_in,
                              void* d_out, int out_size)
{
    const float* xl = (const float*)d_in[0];
    const float* xm = (const float*)d_in[1];
    const float* xr = (const float*)d_in[2];
    float* out = (float*)d_out;

    cv_prep_kernel<<<dim3(HH, BB, 2), 448>>>(xl, xr);
    cv_g_kernel<<<dim3(2, HH, BB), 224>>>(xl, xr);
    cv_lr_out_kernel<<<dim3(HH/4, DD, BB), 416>>>(out);
    cv_lrcost_kernel<<<dim3(4, HH, BB), 256>>>(xm, out);
}

// round 9
// speedup vs baseline: 1.5864x; 1.5603x over previous
#include <cuda_runtime.h>
#include <cuda_fp16.h>

#define BB 2
#define CC 32
#define HH 128
#define WW 416
#define DD 48
#define HW_ (HH*WW)
#define CHW_ (CC*HH*WW)
#define ISCALE 0.05892556509887896f  // 1/sqrt(C*K2) = 1/sqrt(288)

// Emulate the reference's fp16 cast, stored as float32.
__device__ __forceinline__ float h16(float v) {
    return __half2float(__float2half_rn(v));
}

// Device-global scratch (allocation forbidden)
__device__ float g_Al[BB*CHW_];     // normalized 3x3 box sum of xl
__device__ float g_Br[BB*CHW_];     // normalized 3x3 box sum of xr
__device__ float g_nli[BB*HW_];     // 1/max(||patch_l||, eps)
__device__ float g_nri[BB*HW_];
__device__ float g_Grow[BB*DD*HW_]; // horizontal 3-tap of G_{2d} per row

// ---------------------------------------------------------------------------
// Kernel 1: pre-normalized box sums + patch norms. Shuffle-based horizontal
// 3-tap; no smem, no barriers.
// ---------------------------------------------------------------------------
__global__ __launch_bounds__(448) void cv_prep_kernel(
    const float* __restrict__ xl, const float* __restrict__ xr)
{
    const int t    = threadIdx.x;
    const int wi   = t >> 5;
    const int lane = t & 31;
    const int h    = blockIdx.x;
    const int b    = blockIdx.y;
    const int img  = blockIdx.z;
    const float* x = img ? xr : xl;
    float* gbox    = img ? g_Br : g_Al;
    float* gn      = img ? g_nri : g_nli;

    const int u = wi*30 + lane - 1;          // -1 .. 419
    const bool vu = (u >= 0) && (u < WW);
    const bool h0 = (h > 0), h1 = (h < HH - 1);
    const float* base = x + b*CHW_ + h*WW + (vu ? u : 0);

    float ssum = 0.f;
    float boxv[CC];
    #pragma unroll
    for (int c = 0; c < CC; c++) {
        float r0 = (vu && h0) ? __ldg(base + c*HW_ - WW) : 0.f;
        float r1 =  vu        ? __ldg(base + c*HW_)      : 0.f;
        float r2 = (vu && h1) ? __ldg(base + c*HW_ + WW) : 0.f;
        float cs = r0 + r1 + r2;
        ssum += r0*r0 + r1*r1 + r2*r2;
        float csl = __shfl_up_sync(0xffffffffu, cs, 1);
        float csr = __shfl_down_sync(0xffffffffu, cs, 1);
        boxv[c] = csl + cs + csr;
    }
    float sql = __shfl_up_sync(0xffffffffu, ssum, 1);
    float sqr = __shfl_down_sync(0xffffffffu, ssum, 1);
    float ni = 1.f / fmaxf(sqrtf(sql + ssum + sqr), 1e-3f);

    if (lane >= 1 && lane <= 30 && u < WW) {
        float* ob = gbox + b*CHW_ + h*WW + u;
        #pragma unroll
        for (int c = 0; c < CC; c++) ob[c*HW_] = boxv[c] * ni;
        gn[b*HW_ + h*WW + u] = ni;
    }
}

// ---------------------------------------------------------------------------
// Kernel 2: Grow = horizontal 3-tap of G_{2d}(r,u)=dot_c(xl[u],xr[u-2d]).
// fp16-paired smem (one LDS.32 = two disparities), fp32 accumulate,
// warp-shuffle 3-tap, no per-d barriers.
// ---------------------------------------------------------------------------
#define XRW 308   // word k -> {xr[lo+k], xr[lo+k-2]}, lo = u0-96

__global__ __launch_bounds__(224) void cv_g_kernel(
    const float* __restrict__ xl,
    const float* __restrict__ xr)
{
    __shared__ __half2 s_xr2[CC*XRW];   // 39424 B

    const int t    = threadIdx.x;
    const int wi   = t >> 5;
    const int lane = t & 31;
    const int u0   = blockIdx.x * 208;
    const int r    = blockIdx.y;
    const int b    = blockIdx.z;
    const int lo   = u0 - 96;
    const int rbase = b*CHW_ + r*WW;

    for (int i = t; i < CC*77; i += 224) {
        int c = i / 77, q = i % 77;
        int col = lo + 4*q;
        float4 f4 = make_float4(0.f,0.f,0.f,0.f);
        if (col >= 0 && col <= WW-4) f4 = *(const float4*)(xr + rbase + c*HW_ + col);
        float m2 = (col-2 >= 0 && col-2 < WW) ? __ldg(xr + rbase + c*HW_ + col - 2) : 0.f;
        float m1 = (col-1 >= 0 && col-1 < WW) ? __ldg(xr + rbase + c*HW_ + col - 1) : 0.f;
        __half2* dst = s_xr2 + c*XRW + 4*q;
        dst[0] = __floats2half2_rn(f4.x, m2);
        dst[1] = __floats2half2_rn(f4.y, m1);
        dst[2] = __floats2half2_rn(f4.z, f4.x);
        dst[3] = __floats2half2_rn(f4.w, f4.y);
    }
    __syncthreads();

    const int u = u0 - 1 + wi*30 + lane;     // g column this lane computes
    const bool vu = (u >= 0) && (u < WW);
    float rl[CC];
    #pragma unroll
    for (int c = 0; c < CC; c++)
        rl[c] = vu ? __ldg(xl + rbase + c*HW_ + u) : 0.f;

    const bool wr = (lane >= 1) && (lane <= 30) && (u <= u0 + 207) && (u < WW);
    const int obase = b*DD*HW_ + r*WW + (wr ? u : 0);

    for (int dp = 0; dp < 24; dp++) {
        int k = (u - u0) + 96 - 4*dp;        // in [3, 305]
        float g0 = 0.f, g1 = 0.f;
        #pragma unroll
        for (int c = 0; c < CC; c++) {
            float2 v = __half22float2(s_xr2[c*XRW + k]);
            g0 += rl[c] * v.x;               // disparity 2dp
            g1 += rl[c] * v.y;               // disparity 2dp+1
        }
        float s0 = g0 + __shfl_up_sync(0xffffffffu, g0, 1)
                      + __shfl_down_sync(0xffffffffu, g0, 1);
        float s1 = g1 + __shfl_up_sync(0xffffffffu, g1, 1)
                      + __shfl_down_sync(0xffffffffu, g1, 1);
        if (wr) {
            g_Grow[obase + (2*dp)*HW_]   = s0;
            g_Grow[obase + (2*dp+1)*HW_] = s1;
        }
    }
}

// ---------------------------------------------------------------------------
// Kernel 3: LR channel -- vertical 3-tap over Grow + normalization.
// 4 rows per block for ILP.
// ---------------------------------------------------------------------------
__global__ __launch_bounds__(416) void cv_lr_out_kernel(float* __restrict__ out)
{
    const int w  = threadIdx.x;
    const int h0 = blockIdx.x * 4;
    const int d  = blockIdx.y;
    const int b  = blockIdx.z;

    const int ob = (b*3 + 2)*DD*HW_ + d*HW_ + w;
    if (w < d || w >= WW - d) {
        #pragma unroll
        for (int r = 0; r < 4; r++) out[ob + (h0+r)*WW] = 0.f;
        return;
    }
    const int u = w + d;
    const float* gb = g_Grow + (b*DD + d)*HW_ + u;

    float v[6];
    #pragma unroll
    for (int r = 0; r < 6; r++) {
        int row = h0 - 1 + r;
        v[r] = (row >= 0 && row < HH) ? __ldg(gb + row*WW) : 0.f;
    }
    const float* pnl = g_nli + b*HW_ + u;
    const float* pnr = g_nri + b*HW_ + (w - d);
    #pragma unroll
    for (int r = 0; r < 4; r++) {
        int h = h0 + r;
        float s = v[r] + v[r+1] + v[r+2];
        float val = s * __ldg(pnl + h*WW) * __ldg(pnr + h*WW) * ISCALE;
        out[ob + h*WW] = h16(fminf(fmaxf(val, -10.f), 10.f));
    }
}

// ---------------------------------------------------------------------------
// Kernel 4: L and R channels. fp16-paired smem (45.6 KB static), fp32
// accumulate, 256 threads: warp-group 0 does d 0..23, group 1 d 24..47.
// One LDS.32 feeds two disparities. Zero-filled halos -> no guards.
// ---------------------------------------------------------------------------
#define SJ 176   // word j -> {A'[u0+j], A'[u0+j+1]}
#define BJ 180   // word j -> {B'[lo+j], B'[lo+j-1]}, lo = u0-48

__global__ __launch_bounds__(256) void cv_lrcost_kernel(
    const float* __restrict__ xm, float* __restrict__ out)
{
    __shared__ __half2 s_A2[CC*SJ];   // 22528 B
    __shared__ __half2 s_B2[CC*BJ];   // 23040 B

    const int t  = threadIdx.x;
    const int u0 = blockIdx.x * 128;
    const int h  = blockIdx.y;
    const int b  = blockIdx.z;
    const int grow = b*CHW_ + h*WW;

    for (int i = t; i < CC*44; i += 256) {
        int c = i / 44, q = i % 44;
        int col = u0 + 4*q;
        float4 a4 = make_float4(0.f,0.f,0.f,0.f);
        if (col <= WW-4) a4 = *(const float4*)(g_Al + grow + c*HW_ + col);
        float a5 = (col+4 < WW) ? __ldg(g_Al + grow + c*HW_ + col + 4) : 0.f;
        __half2* dst = s_A2 + c*SJ + 4*q;
        dst[0] = __floats2half2_rn(a4.x, a4.y);
        dst[1] = __floats2half2_rn(a4.y, a4.z);
        dst[2] = __floats2half2_rn(a4.z, a4.w);
        dst[3] = __floats2half2_rn(a4.w, a5);
    }
    for (int i = t; i < CC*45; i += 256) {
        int c = i / 45, q = i % 45;
        int col = u0 - 48 + 4*q;
        float4 b4 = make_float4(0.f,0.f,0.f,0.f);
        if (col >= 0 && col <= WW-4) b4 = *(const float4*)(g_Br + grow + c*HW_ + col);
        float bm1 = (col-1 >= 0 && col-1 < WW) ? __ldg(g_Br + grow + c*HW_ + col - 1) : 0.f;
        __half2* dst = s_B2 + c*BJ + 4*q;
        dst[0] = __floats2half2_rn(b4.x, bm1);
        dst[1] = __floats2half2_rn(b4.y, b4.x);
        dst[2] = __floats2half2_rn(b4.z, b4.y);
        dst[3] = __floats2half2_rn(b4.w, b4.z);
    }
    __syncthreads();

    const int tw = t & 127;        // w within tile
    const int d0 = (t >> 7) * 24;  // 0 or 24
    const int w  = u0 + tw;
    if (w >= WW) return;

    float f[CC];
    {
        float ss = 0.f;
        const float* pm = xm + b*CHW_ + h*WW + w;
        #pragma unroll
        for (int c = 0; c < CC; c++) {
            float v = __ldg(pm + c*HW_);
            f[c] = v; ss += v*v;
        }
        float nf = ISCALE / fmaxf(sqrtf(ss), 1e-3f);
        #pragma unroll
        for (int c = 0; c < CC; c++) f[c] *= nf;
    }

    const int ob = (b*3)*DD*HW_ + h*WW + w;   // channel-L base at d=0
    for (int i = 0; i < 12; i++) {
        const int d = d0 + 2*i;                  // even disparity of the pair
        const __half2* sa = s_A2 + (tw + d);     // .x -> d, .y -> d+1
        const __half2* sb = s_B2 + (tw - d + 48);
        float aL0 = 0.f, aL1 = 0.f, aR0 = 0.f, aR1 = 0.f;
        #pragma unroll
        for (int c = 0; c < CC; c++) {
            float2 av = __half22float2(sa[c*SJ]);
            aL0 += f[c] * av.x;
            aL1 += f[c] * av.y;
            float2 bv = __half22float2(sb[c*BJ]);
            aR0 += f[c] * bv.x;
            aR1 += f[c] * bv.y;
        }
        int o = ob + d*HW_;
        out[o]              = h16(fminf(fmaxf(aL0, -10.f), 10.f));
        out[o + HW_]        = h16(fminf(fmaxf(aL1, -10.f), 10.f));
        out[o + DD*HW_]     = h16(fminf(fmaxf(aR0, -10.f), 10.f));
        out[o + (DD+1)*HW_] = h16(fminf(fmaxf(aR1, -10.f), 10.f));
    }
}

// ---------------------------------------------------------------------------
extern "C" void kernel_launch(void* const* d_in, const int* in_sizes, int n_in,
                              void* d_out, int out_size)
{
    const float* xl = (const float*)d_in[0];
    const float* xm = (const float*)d_in[1];
    const float* xr = (const float*)d_in[2];
    float* out = (float*)d_out;

    cv_prep_kernel<<<dim3(HH, BB, 2), 448>>>(xl, xr);
    cv_g_kernel<<<dim3(2, HH, BB), 224>>>(xl, xr);
    cv_lr_out_kernel<<<dim3(HH/4, DD, BB), 416>>>(out);
    cv_lrcost_kernel<<<dim3(4, HH, BB), 256>>>(xm, out);
}

// round 10
// speedup vs baseline: 1.8257x; 1.1509x over previous
#include <cuda_runtime.h>
#include <cuda_fp16.h>
#include <cstdint>

#define BB 2
#define CC 32
#define HH 128
#define WW 416
#define DD 48
#define HW_ (HH*WW)
#define CHW_ (CC*HH*WW)
#define ISCALE 0.05892556509887896f  // 1/sqrt(C*K2) = 1/sqrt(288)

// Emulate the reference's fp16 cast, stored as float32.
__device__ __forceinline__ float h16(float v) {
    return __half2float(__float2half_rn(v));
}

#define MMA16816(c0,c1,c2,c3,a0,a1,a2,a3,b0,b1) \
  asm volatile("mma.sync.aligned.m16n8k16.row.col.f32.f16.f16.f32 " \
    "{%0,%1,%2,%3}, {%4,%5,%6,%7}, {%8,%9}, {%0,%1,%2,%3};" \
    : "+f"(c0), "+f"(c1), "+f"(c2), "+f"(c3) \
    : "r"(a0), "r"(a1), "r"(a2), "r"(a3), "r"(b0), "r"(b1))

// Device-global scratch (allocation forbidden)
__device__ float g_Al[BB*CHW_];     // normalized 3x3 box sum of xl
__device__ float g_Br[BB*CHW_];     // normalized 3x3 box sum of xr
__device__ float g_nli[BB*HW_];     // 1/max(||patch_l||, eps)
__device__ float g_nri[BB*HW_];
__device__ float g_Grow[BB*DD*HW_]; // horizontal 3-tap of G_{2d} per row

// ---------------------------------------------------------------------------
// Kernel 1: pre-normalized box sums + patch norms. Shuffle-based horizontal
// 3-tap; no smem, no barriers.
// ---------------------------------------------------------------------------
__global__ __launch_bounds__(448) void cv_prep_kernel(
    const float* __restrict__ xl, const float* __restrict__ xr)
{
    const int t    = threadIdx.x;
    const int wi   = t >> 5;
    const int lane = t & 31;
    const int h    = blockIdx.x;
    const int b    = blockIdx.y;
    const int img  = blockIdx.z;
    const float* x = img ? xr : xl;
    float* gbox    = img ? g_Br : g_Al;
    float* gn      = img ? g_nri : g_nli;

    const int u = wi*30 + lane - 1;          // -1 .. 419
    const bool vu = (u >= 0) && (u < WW);
    const bool h0 = (h > 0), h1 = (h < HH - 1);
    const float* base = x + b*CHW_ + h*WW + (vu ? u : 0);

    float ssum = 0.f;
    float boxv[CC];
    #pragma unroll
    for (int c = 0; c < CC; c++) {
        float r0 = (vu && h0) ? __ldg(base + c*HW_ - WW) : 0.f;
        float r1 =  vu        ? __ldg(base + c*HW_)      : 0.f;
        float r2 = (vu && h1) ? __ldg(base + c*HW_ + WW) : 0.f;
        float cs = r0 + r1 + r2;
        ssum += r0*r0 + r1*r1 + r2*r2;
        float csl = __shfl_up_sync(0xffffffffu, cs, 1);
        float csr = __shfl_down_sync(0xffffffffu, cs, 1);
        boxv[c] = csl + cs + csr;
    }
    float sql = __shfl_up_sync(0xffffffffu, ssum, 1);
    float sqr = __shfl_down_sync(0xffffffffu, ssum, 1);
    float ni = 1.f / fmaxf(sqrtf(sql + ssum + sqr), 1e-3f);

    if (lane >= 1 && lane <= 30 && u < WW) {
        float* ob = gbox + b*CHW_ + h*WW + u;
        #pragma unroll
        for (int c = 0; c < CC; c++) ob[c*HW_] = boxv[c] * ni;
        gn[b*HW_ + h*WW + u] = ni;
    }
}

// ---------------------------------------------------------------------------
// Kernel 2: Grow = horizontal 3-tap of G_{2d}(r,u)=dot_c(xl[u],xr[u-2d]).
// fp16-paired smem (one LDS.32 = two disparities), fp32 accumulate,
// warp-shuffle 3-tap, no per-d barriers.
// ---------------------------------------------------------------------------
#define XRW 308   // word k -> {xr[lo+k], xr[lo+k-2]}, lo = u0-96

__global__ __launch_bounds__(224) void cv_g_kernel(
    const float* __restrict__ xl,
    const float* __restrict__ xr)
{
    __shared__ __half2 s_xr2[CC*XRW];   // 39424 B

    const int t    = threadIdx.x;
    const int wi   = t >> 5;
    const int lane = t & 31;
    const int u0   = blockIdx.x * 208;
    const int r    = blockIdx.y;
    const int b    = blockIdx.z;
    const int lo   = u0 - 96;
    const int rbase = b*CHW_ + r*WW;

    for (int i = t; i < CC*77; i += 224) {
        int c = i / 77, q = i % 77;
        int col = lo + 4*q;
        float4 f4 = make_float4(0.f,0.f,0.f,0.f);
        if (col >= 0 && col <= WW-4) f4 = *(const float4*)(xr + rbase + c*HW_ + col);
        float m2 = (col-2 >= 0 && col-2 < WW) ? __ldg(xr + rbase + c*HW_ + col - 2) : 0.f;
        float m1 = (col-1 >= 0 && col-1 < WW) ? __ldg(xr + rbase + c*HW_ + col - 1) : 0.f;
        __half2* dst = s_xr2 + c*XRW + 4*q;
        dst[0] = __floats2half2_rn(f4.x, m2);
        dst[1] = __floats2half2_rn(f4.y, m1);
        dst[2] = __floats2half2_rn(f4.z, f4.x);
        dst[3] = __floats2half2_rn(f4.w, f4.y);
    }
    __syncthreads();

    const int u = u0 - 1 + wi*30 + lane;     // g column this lane computes
    const bool vu = (u >= 0) && (u < WW);
    float rl[CC];
    #pragma unroll
    for (int c = 0; c < CC; c++)
        rl[c] = vu ? __ldg(xl + rbase + c*HW_ + u) : 0.f;

    const bool wr = (lane >= 1) && (lane <= 30) && (u <= u0 + 207) && (u < WW);
    const int obase = b*DD*HW_ + r*WW + (wr ? u : 0);

    for (int dp = 0; dp < 24; dp++) {
        int k = (u - u0) + 96 - 4*dp;        // in [3, 305]
        float g0 = 0.f, g1 = 0.f;
        #pragma unroll
        for (int c = 0; c < CC; c++) {
            float2 v = __half22float2(s_xr2[c*XRW + k]);
            g0 += rl[c] * v.x;               // disparity 2dp
            g1 += rl[c] * v.y;               // disparity 2dp+1
        }
        float s0 = g0 + __shfl_up_sync(0xffffffffu, g0, 1)
                      + __shfl_down_sync(0xffffffffu, g0, 1);
        float s1 = g1 + __shfl_up_sync(0xffffffffu, g1, 1)
                      + __shfl_down_sync(0xffffffffu, g1, 1);
        if (wr) {
            g_Grow[obase + (2*dp)*HW_]   = s0;
            g_Grow[obase + (2*dp+1)*HW_] = s1;
        }
    }
}

// ---------------------------------------------------------------------------
// Kernel 3: LR channel -- vertical 3-tap over Grow + normalization.
// 4 rows per block for ILP.
// ---------------------------------------------------------------------------
__global__ __launch_bounds__(416) void cv_lr_out_kernel(float* __restrict__ out)
{
    const int w  = threadIdx.x;
    const int h0 = blockIdx.x * 4;
    const int d  = blockIdx.y;
    const int b  = blockIdx.z;

    const int ob = (b*3 + 2)*DD*HW_ + d*HW_ + w;
    if (w < d || w >= WW - d) {
        #pragma unroll
        for (int r = 0; r < 4; r++) out[ob + (h0+r)*WW] = 0.f;
        return;
    }
    const int u = w + d;
    const float* gb = g_Grow + (b*DD + d)*HW_ + u;

    float v[6];
    #pragma unroll
    for (int r = 0; r < 6; r++) {
        int row = h0 - 1 + r;
        v[r] = (row >= 0 && row < HH) ? __ldg(gb + row*WW) : 0.f;
    }
    const float* pnl = g_nli + b*HW_ + u;
    const float* pnr = g_nri + b*HW_ + (w - d);
    #pragma unroll
    for (int r = 0; r < 4; r++) {
        int h = h0 + r;
        float s = v[r] + v[r+1] + v[r+2];
        float val = s * __ldg(pnl + h*WW) * __ldg(pnr + h*WW) * ISCALE;
        out[ob + h*WW] = h16(fminf(fmaxf(val, -10.f), 10.f));
    }
}

// ---------------------------------------------------------------------------
// Kernel 4: L and R channels via tensor cores (m16n8k16 HMMA, fp32 accum).
// Per (b,h,128-tile): O = F^T(128x32) * W(32x176) band-extracted.
// Each warp owns one 16-row m-tile and its 8 n-tiles (j in [16mw,16mw+63]).
// smem: half arrays [idx][32c] padded to 40 halves (20 words) per row --
// lane-group word index g*20+tt is conflict-free.
// ---------------------------------------------------------------------------
#define TWH 40   // padded row stride in halves
#define TWW 20   // in 32-bit words

__global__ __launch_bounds__(256) void cv_lrcost_kernel(
    const float* __restrict__ xm, float* __restrict__ out)
{
    __shared__ __half s_F [128*TWH];   // [w_local][c]  10240 B
    __shared__ __half s_WA[176*TWH];   // [j][c], A' at col u0+j      14080 B
    __shared__ __half s_WB[176*TWH];   // [j][c], B' at col u0-48+j   14080 B

    const int t  = threadIdx.x;
    const int u0 = blockIdx.x * 128;
    const int h  = blockIdx.y;
    const int b  = blockIdx.z;
    const int grow = b*CHW_ + h*WW;

    // Fill operand windows (transposed to [j][c], zero outside image).
    for (int i = t; i < CC*176; i += 256) {
        int c = i / 176, j = i % 176;
        int colA = u0 + j;
        float va = (colA < WW) ? __ldg(g_Al + grow + c*HW_ + colA) : 0.f;
        s_WA[j*TWH + c] = __float2half_rn(va);
        int colB = u0 - 48 + j;
        float vb = (colB >= 0 && colB < WW) ? __ldg(g_Br + grow + c*HW_ + colB) : 0.f;
        s_WB[j*TWH + c] = __float2half_rn(vb);
    }
    // Fill F (normalized xm, ISCALE folded), row-major [w_local][c].
    if (t < 128) {
        const int w = u0 + t;
        float fv[CC];
        if (w < WW) {
            float ss = 0.f;
            const float* pm = xm + grow + w;
            #pragma unroll
            for (int c = 0; c < CC; c++) { fv[c] = __ldg(pm + c*HW_); ss += fv[c]*fv[c]; }
            float nf = ISCALE / fmaxf(sqrtf(ss), 1e-3f);
            #pragma unroll
            for (int c = 0; c < CC; c++) fv[c] *= nf;
        } else {
            #pragma unroll
            for (int c = 0; c < CC; c++) fv[c] = 0.f;
        }
        __half2* fr = (__half2*)(s_F + t*TWH);
        #pragma unroll
        for (int k = 0; k < 16; k++) fr[k] = __floats2half2_rn(fv[2*k], fv[2*k+1]);
    }
    __syncthreads();

    const int wid  = t >> 5;
    const int lane = t & 31;
    const int g    = lane >> 2;      // group 0..7
    const int tt   = lane & 3;       // 0..3
    const int wl0  = wid * 16;       // m-tile base (w_local)
    if (u0 + wl0 >= WW) return;      // no barriers after this point

    const uint32_t* Fw  = (const uint32_t*)s_F;
    const uint32_t* WAw = (const uint32_t*)s_WA;
    const uint32_t* WBw = (const uint32_t*)s_WB;

    // A fragments (two k-steps), rows wl0+g and wl0+g+8.
    const int ra = (wl0 + g) * TWW + tt;
    const int rb = ra + 8 * TWW;
    const uint32_t a0 = Fw[ra],    a1 = Fw[rb],    a2 = Fw[ra+4],  a3 = Fw[rb+4];
    const uint32_t a4 = Fw[ra+8],  a5 = Fw[rb+8],  a6 = Fw[ra+12], a7 = Fw[rb+12];

    const int obL = (b*3)*DD*HW_ + h*WW + u0;   // + w_local + d*HW_
    const int rl0 = wl0 + g;                    // w_local of c0/c1
    const int rl1 = rl0 + 8;                    // w_local of c2/c3

    #pragma unroll
    for (int nn = 0; nn < 8; nn++) {
        const int jr = wl0 + 8*nn;              // j base of this n-tile
        const int jb = (jr + g) * TWW + tt;
        const int j0 = jr + 2*tt, j1 = j0 + 1;

        // ---- L side ----
        {
            uint32_t b0 = WAw[jb], b1 = WAw[jb+4], b2 = WAw[jb+8], b3 = WAw[jb+12];
            float c0 = 0.f, c1 = 0.f, c2 = 0.f, c3 = 0.f;
            MMA16816(c0,c1,c2,c3, a0,a1,a2,a3, b0,b1);
            MMA16816(c0,c1,c2,c3, a4,a5,a6,a7, b2,b3);
            int d;
            d = j0 - rl0; if (d >= 0 && d < DD)
                out[obL + rl0 + d*HW_] = h16(fminf(fmaxf(c0, -10.f), 10.f));
            d = j1 - rl0; if (d >= 0 && d < DD)
                out[obL + rl0 + d*HW_] = h16(fminf(fmaxf(c1, -10.f), 10.f));
            d = j0 - rl1; if (d >= 0 && d < DD)
                out[obL + rl1 + d*HW_] = h16(fminf(fmaxf(c2, -10.f), 10.f));
            d = j1 - rl1; if (d >= 0 && d < DD)
                out[obL + rl1 + d*HW_] = h16(fminf(fmaxf(c3, -10.f), 10.f));
        }
        // ---- R side ----
        {
            uint32_t b0 = WBw[jb], b1 = WBw[jb+4], b2 = WBw[jb+8], b3 = WBw[jb+12];
            float c0 = 0.f, c1 = 0.f, c2 = 0.f, c3 = 0.f;
            MMA16816(c0,c1,c2,c3, a0,a1,a2,a3, b0,b1);
            MMA16816(c0,c1,c2,c3, a4,a5,a6,a7, b2,b3);
            int d;
            d = rl0 + 48 - j0; if (d >= 0 && d < DD)
                out[obL + rl0 + (DD + d)*HW_] = h16(fminf(fmaxf(c0, -10.f), 10.f));
            d = rl0 + 48 - j1; if (d >= 0 && d < DD)
                out[obL + rl0 + (DD + d)*HW_] = h16(fminf(fmaxf(c1, -10.f), 10.f));
            d = rl1 + 48 - j0; if (d >= 0 && d < DD)
                out[obL + rl1 + (DD + d)*HW_] = h16(fminf(fmaxf(c2, -10.f), 10.f));
            d = rl1 + 48 - j1; if (d >= 0 && d < DD)
                out[obL + rl1 + (DD + d)*HW_] = h16(fminf(fmaxf(c3, -10.f), 10.f));
        }
    }
}

// ---------------------------------------------------------------------------
extern "C" void kernel_launch(void* const* d_in, const int* in_sizes, int n_in,
                              void* d_out, int out_size)
{
    const float* xl = (const float*)d_in[0];
    const float* xm = (const float*)d_in[1];
    const float* xr = (const float*)d_in[2];
    float* out = (float*)d_out;

    cv_prep_kernel<<<dim3(HH, BB, 2), 448>>>(xl, xr);
    cv_g_kernel<<<dim3(2, HH, BB), 224>>>(xl, xr);
    cv_lr_out_kernel<<<dim3(HH/4, DD, BB), 416>>>(out);
    cv_lrcost_kernel<<<dim3(4, HH, BB), 256>>>(xm, out);
}

// round 11
// speedup vs baseline: 1.9142x; 1.0484x over previous
#include <cuda_runtime.h>
#include <cuda_fp16.h>
#include <cstdint>

#define BB 2
#define CC 32
#define HH 128
#define WW 416
#define DD 48
#define HW_ (HH*WW)
#define CHW_ (CC*HH*WW)
#define ISCALE 0.05892556509887896f  // 1/sqrt(C*K2) = 1/sqrt(288)

// Emulate the reference's fp16 cast, stored as float32.
__device__ __forceinline__ float h16(float v) {
    return __half2float(__float2half_rn(v));
}

#define MMA16816(c0,c1,c2,c3,a0,a1,a2,a3,b0,b1) \
  asm volatile("mma.sync.aligned.m16n8k16.row.col.f32.f16.f16.f32 " \
    "{%0,%1,%2,%3}, {%4,%5,%6,%7}, {%8,%9}, {%0,%1,%2,%3};" \
    : "+f"(c0), "+f"(c1), "+f"(c2), "+f"(c3) \
    : "r"(a0), "r"(a1), "r"(a2), "r"(a3), "r"(b0), "r"(b1))

#define TWH 40   // operand row stride in halves
#define TWW 20   // in 32-bit words

// Device-global scratch (allocation forbidden)
__device__ float g_Al[BB*CHW_];     // normalized 3x3 box sum of xl
__device__ float g_Br[BB*CHW_];     // normalized 3x3 box sum of xr
__device__ float g_nli[BB*HW_];     // 1/max(||patch_l||, eps)
__device__ float g_nri[BB*HW_];
__device__ float g_Grow[BB*DD*HW_]; // horizontal 3-tap of G_{2d} per row

// ---------------------------------------------------------------------------
// Kernel 1: pre-normalized box sums + patch norms (unchanged, proven).
// ---------------------------------------------------------------------------
__global__ __launch_bounds__(448) void cv_prep_kernel(
    const float* __restrict__ xl, const float* __restrict__ xr)
{
    const int t    = threadIdx.x;
    const int wi   = t >> 5;
    const int lane = t & 31;
    const int h    = blockIdx.x;
    const int b    = blockIdx.y;
    const int img  = blockIdx.z;
    const float* x = img ? xr : xl;
    float* gbox    = img ? g_Br : g_Al;
    float* gn      = img ? g_nri : g_nli;

    const int u = wi*30 + lane - 1;          // -1 .. 419
    const bool vu = (u >= 0) && (u < WW);
    const bool h0 = (h > 0), h1 = (h < HH - 1);
    const float* base = x + b*CHW_ + h*WW + (vu ? u : 0);

    float ssum = 0.f;
    float boxv[CC];
    #pragma unroll
    for (int c = 0; c < CC; c++) {
        float r0 = (vu && h0) ? __ldg(base + c*HW_ - WW) : 0.f;
        float r1 =  vu        ? __ldg(base + c*HW_)      : 0.f;
        float r2 = (vu && h1) ? __ldg(base + c*HW_ + WW) : 0.f;
        float cs = r0 + r1 + r2;
        ssum += r0*r0 + r1*r1 + r2*r2;
        float csl = __shfl_up_sync(0xffffffffu, cs, 1);
        float csr = __shfl_down_sync(0xffffffffu, cs, 1);
        boxv[c] = csl + cs + csr;
    }
    float sql = __shfl_up_sync(0xffffffffu, ssum, 1);
    float sqr = __shfl_down_sync(0xffffffffu, ssum, 1);
    float ni = 1.f / fmaxf(sqrtf(sql + ssum + sqr), 1e-3f);

    if (lane >= 1 && lane <= 30 && u < WW) {
        float* ob = gbox + b*CHW_ + h*WW + u;
        #pragma unroll
        for (int c = 0; c < CC; c++) ob[c*HW_] = boxv[c] * ni;
        gn[b*HW_ + h*WW + u] = ni;
    }
}

// ---------------------------------------------------------------------------
// Kernel 2: Grow via HMMA. Parity identity: G(2p+q, d) = sum_c XLq[c,p] *
// XRq[c,p-d], i.e. the same banded-GEMM shape as lrcost's R side.
// Raw G staged in smem [u_loc][d] (fp16), horizontal 3-tap in copy-out.
// Dynamic smem: XL 2*112*40 + XR 2*160*40 + stage 224*50 halves = 65920 B.
// ---------------------------------------------------------------------------
#define GP  112   // p values staged per parity
#define GJ  160   // XR window per parity (m = P0-48+j)
#define GDS 50    // staging stride in halves

__global__ __launch_bounds__(256) void cv_g_kernel(
    const float* __restrict__ xl,
    const float* __restrict__ xr)
{
    extern __shared__ __half gsm[];
    __half* s_XL = gsm;                          // [q][p_loc][c]
    __half* s_XR = gsm + 2*GP*TWH;               // [q][j][c]
    __half* s_G  = gsm + 2*GP*TWH + 2*GJ*TWH;    // [u_loc][d]

    const int t  = threadIdx.x;
    const int u0 = blockIdx.x * 208;
    const int r  = blockIdx.y;
    const int b  = blockIdx.z;
    const int P0 = u0/2 - 4;         // staged u range: [2P0, 2P0+224)
    const int rbase = b*CHW_ + r*WW;

    // Fill XL (u in [2P0, 2P0+224)) and XR (u in [2P0-96, 2P0+224)).
    for (int i = t; i < 224*CC; i += 256) {
        int c = i / 224, uu = i % 224;
        int u = 2*P0 + uu;
        float v = (u >= 0 && u < WW) ? __ldg(xl + rbase + c*HW_ + u) : 0.f;
        int q = uu & 1, p = uu >> 1;
        s_XL[q*GP*TWH + p*TWH + c] = __float2half_rn(v);
    }
    for (int i = t; i < 320*CC; i += 256) {
        int c = i / 320, uu = i % 320;
        int u = 2*P0 - 96 + uu;
        float v = (u >= 0 && u < WW) ? __ldg(xr + rbase + c*HW_ + u) : 0.f;
        int q = uu & 1, j = uu >> 1;
        s_XR[q*GJ*TWH + j*TWH + c] = __float2half_rn(v);
    }
    __syncthreads();

    const int wid  = t >> 5;
    const int lane = t & 31;
    const int g    = lane >> 2;
    const int tt   = lane & 3;

    for (int job = wid; job < 14; job += 8) {
        const int q = job & 1;
        const int i = job >> 1;                  // m-tile 0..6
        const uint32_t* XLw = (const uint32_t*)(s_XL + q*GP*TWH);
        const uint32_t* XRw = (const uint32_t*)(s_XR + q*GJ*TWH);

        const int rl0 = 16*i + g, rl1 = rl0 + 8; // p_loc rows
        const int ra = rl0 * TWW + tt;
        const int rb = ra + 8 * TWW;
        const uint32_t a0 = XLw[ra],   a1 = XLw[rb],   a2 = XLw[ra+4],  a3 = XLw[rb+4];
        const uint32_t a4 = XLw[ra+8], a5 = XLw[rb+8], a6 = XLw[ra+12], a7 = XLw[rb+12];

        const int ub0 = (2*rl0 + q) * GDS;       // staging row of rl0
        const int ub1 = (2*rl1 + q) * GDS;

        #pragma unroll
        for (int nn = 0; nn < 8; nn++) {
            const int jr = 16*i + 8*nn;
            const int jb = (jr + g) * TWW + tt;
            const int j0 = jr + 2*tt, j1 = j0 + 1;
            uint32_t b0 = XRw[jb], b1 = XRw[jb+4], b2 = XRw[jb+8], b3 = XRw[jb+12];
            float c0 = 0.f, c1 = 0.f, c2 = 0.f, c3 = 0.f;
            MMA16816(c0,c1,c2,c3, a0,a1,a2,a3, b0,b1);
            MMA16816(c0,c1,c2,c3, a4,a5,a6,a7, b2,b3);
            int d;
            d = rl0 + 48 - j0; if (d >= 0 && d < DD) s_G[ub0 + d] = __float2half_rn(c0);
            d = rl0 + 48 - j1; if (d >= 0 && d < DD) s_G[ub0 + d] = __float2half_rn(c1);
            d = rl1 + 48 - j0; if (d >= 0 && d < DD) s_G[ub1 + d] = __float2half_rn(c2);
            d = rl1 + 48 - j1; if (d >= 0 && d < DD) s_G[ub1 + d] = __float2half_rn(c3);
        }
    }
    __syncthreads();

    // Horizontal 3-tap + coalesced store.
    for (int idx = t; idx < DD*208; idx += 256) {
        int d = idx / 208, ul = idx % 208;
        int uloc = ul + 8;                        // u = u0 + ul
        float s = __half2float(s_G[(uloc-1)*GDS + d])
                + __half2float(s_G[ uloc   *GDS + d])
                + __half2float(s_G[(uloc+1)*GDS + d]);
        g_Grow[(b*DD + d)*HW_ + r*WW + u0 + ul] = s;
    }
}

// ---------------------------------------------------------------------------
// Kernel 3: LR channel -- vertical 3-tap over Grow + normalization (proven).
// ---------------------------------------------------------------------------
__global__ __launch_bounds__(416) void cv_lr_out_kernel(float* __restrict__ out)
{
    const int w  = threadIdx.x;
    const int h0 = blockIdx.x * 4;
    const int d  = blockIdx.y;
    const int b  = blockIdx.z;

    const int ob = (b*3 + 2)*DD*HW_ + d*HW_ + w;
    if (w < d || w >= WW - d) {
        #pragma unroll
        for (int r = 0; r < 4; r++) out[ob + (h0+r)*WW] = 0.f;
        return;
    }
    const int u = w + d;
    const float* gb = g_Grow + (b*DD + d)*HW_ + u;

    float v[6];
    #pragma unroll
    for (int r = 0; r < 6; r++) {
        int row = h0 - 1 + r;
        v[r] = (row >= 0 && row < HH) ? __ldg(gb + row*WW) : 0.f;
    }
    const float* pnl = g_nli + b*HW_ + u;
    const float* pnr = g_nri + b*HW_ + (w - d);
    #pragma unroll
    for (int r = 0; r < 4; r++) {
        int h = h0 + r;
        float s = v[r] + v[r+1] + v[r+2];
        float val = s * __ldg(pnl + h*WW) * __ldg(pnr + h*WW) * ISCALE;
        out[ob + h*WW] = h16(fminf(fmaxf(val, -10.f), 10.f));
    }
}

// ---------------------------------------------------------------------------
// Kernel 4: L/R channels via HMMA with de-scattered epilogue: results are
// clamped+fp16-rounded in registers (bit-exact with final output), staged
// in smem [w][dp] (dp = d for L, 48+d for R), then copied out coalesced.
// Dynamic smem: (128 + 176 + 176)*40 + 128*98 halves = 63488 B.
// ---------------------------------------------------------------------------
#define WS2 98   // staging stride in halves (96 dp + pad; 49 words -> cf)

__global__ __launch_bounds__(256) void cv_lrcost_kernel(
    const float* __restrict__ xm, float* __restrict__ out)
{
    extern __shared__ __half lsm[];
    __half* s_F  = lsm;                 // [w_local][c]
    __half* s_WA = lsm + 128*TWH;       // [j][c], A' at col u0+j
    __half* s_WB = lsm + (128+176)*TWH; // [j][c], B' at col u0-48+j
    __half* s_S  = lsm + (128+176+176)*TWH;  // [w][dp]

    const int t  = threadIdx.x;
    const int u0 = blockIdx.x * 128;
    const int h  = blockIdx.y;
    const int b  = blockIdx.z;
    const int grow = b*CHW_ + h*WW;

    for (int i = t; i < CC*176; i += 256) {
        int c = i / 176, j = i % 176;
        int colA = u0 + j;
        float va = (colA < WW) ? __ldg(g_Al + grow + c*HW_ + colA) : 0.f;
        s_WA[j*TWH + c] = __float2half_rn(va);
        int colB = u0 - 48 + j;
        float vb = (colB >= 0 && colB < WW) ? __ldg(g_Br + grow + c*HW_ + colB) : 0.f;
        s_WB[j*TWH + c] = __float2half_rn(vb);
    }
    if (t < 128) {
        const int w = u0 + t;
        float fv[CC];
        if (w < WW) {
            float ss = 0.f;
            const float* pm = xm + grow + w;
            #pragma unroll
            for (int c = 0; c < CC; c++) { fv[c] = __ldg(pm + c*HW_); ss += fv[c]*fv[c]; }
            float nf = ISCALE / fmaxf(sqrtf(ss), 1e-3f);
            #pragma unroll
            for (int c = 0; c < CC; c++) fv[c] *= nf;
        } else {
            #pragma unroll
            for (int c = 0; c < CC; c++) fv[c] = 0.f;
        }
        __half2* fr = (__half2*)(s_F + t*TWH);
        #pragma unroll
        for (int k = 0; k < 16; k++) fr[k] = __floats2half2_rn(fv[2*k], fv[2*k+1]);
    }
    __syncthreads();

    const int wid  = t >> 5;
    const int lane = t & 31;
    const int g    = lane >> 2;
    const int tt   = lane & 3;
    const int wl0  = wid * 16;

    const uint32_t* Fw  = (const uint32_t*)s_F;
    const uint32_t* WAw = (const uint32_t*)s_WA;
    const uint32_t* WBw = (const uint32_t*)s_WB;

    const int rl0 = wl0 + g, rl1 = rl0 + 8;
    const int ra = rl0 * TWW + tt;
    const int rb = ra + 8 * TWW;
    const uint32_t a0 = Fw[ra],    a1 = Fw[rb],    a2 = Fw[ra+4],  a3 = Fw[rb+4];
    const uint32_t a4 = Fw[ra+8],  a5 = Fw[rb+8],  a6 = Fw[ra+12], a7 = Fw[rb+12];

    const int sb0 = rl0 * WS2, sb1 = rl1 * WS2;

    #pragma unroll
    for (int nn = 0; nn < 8; nn++) {
        const int jr = wl0 + 8*nn;
        const int jb = (jr + g) * TWW + tt;
        const int j0 = jr + 2*tt, j1 = j0 + 1;

        {   // L side: dp = j - rl
            uint32_t b0 = WAw[jb], b1 = WAw[jb+4], b2 = WAw[jb+8], b3 = WAw[jb+12];
            float c0 = 0.f, c1 = 0.f, c2 = 0.f, c3 = 0.f;
            MMA16816(c0,c1,c2,c3, a0,a1,a2,a3, b0,b1);
            MMA16816(c0,c1,c2,c3, a4,a5,a6,a7, b2,b3);
            int d;
            d = j0 - rl0; if (d >= 0 && d < DD)
                s_S[sb0 + d] = __float2half_rn(fminf(fmaxf(c0, -10.f), 10.f));
            d = j1 - rl0; if (d >= 0 && d < DD)
                s_S[sb0 + d] = __float2half_rn(fminf(fmaxf(c1, -10.f), 10.f));
            d = j0 - rl1; if (d >= 0 && d < DD)
                s_S[sb1 + d] = __float2half_rn(fminf(fmaxf(c2, -10.f), 10.f));
            d = j1 - rl1; if (d >= 0 && d < DD)
                s_S[sb1 + d] = __float2half_rn(fminf(fmaxf(c3, -10.f), 10.f));
        }
        {   // R side: dp = 48 + (rl + 48 - j)
            uint32_t b0 = WBw[jb], b1 = WBw[jb+4], b2 = WBw[jb+8], b3 = WBw[jb+12];
            float c0 = 0.f, c1 = 0.f, c2 = 0.f, c3 = 0.f;
            MMA16816(c0,c1,c2,c3, a0,a1,a2,a3, b0,b1);
            MMA16816(c0,c1,c2,c3, a4,a5,a6,a7, b2,b3);
            int d;
            d = rl0 + 48 - j0; if (d >= 0 && d < DD)
                s_S[sb0 + 48 + d] = __float2half_rn(fminf(fmaxf(c0, -10.f), 10.f));
            d = rl0 + 48 - j1; if (d >= 0 && d < DD)
                s_S[sb0 + 48 + d] = __float2half_rn(fminf(fmaxf(c1, -10.f), 10.f));
            d = rl1 + 48 - j0; if (d >= 0 && d < DD)
                s_S[sb1 + 48 + d] = __float2half_rn(fminf(fmaxf(c2, -10.f), 10.f));
            d = rl1 + 48 - j1; if (d >= 0 && d < DD)
                s_S[sb1 + 48 + d] = __float2half_rn(fminf(fmaxf(c3, -10.f), 10.f));
        }
    }
    __syncthreads();

    // Coalesced copy-out: channel L = dp [0,48), channel R = dp [48,96).
    const int wlim = min(128, WW - u0);
    const int obase = (b*3)*DD*HW_ + h*WW + u0;
    for (int i = t; i < 96*128; i += 256) {
        int dp = i >> 7, w = i & 127;
        if (w < wlim) {
            float v = __half2float(s_S[w*WS2 + dp]);
            out[obase + dp*HW_ + w] = v;   // dp<48 -> L d=dp; dp>=48 -> R d=dp-48
        }
    }
}

// ---------------------------------------------------------------------------
extern "C" void kernel_launch(void* const* d_in, const int* in_sizes, int n_in,
                              void* d_out, int out_size)
{
    const float* xl = (const float*)d_in[0];
    const float* xm = (const float*)d_in[1];
    const float* xr = (const float*)d_in[2];
    float* out = (float*)d_out;

    const int smem_g  = (2*GP*TWH + 2*GJ*TWH + 224*GDS) * (int)sizeof(__half);   // 65920
    const int smem_lr = ((128+176+176)*TWH + 128*WS2) * (int)sizeof(__half);     // 63488
    cudaFuncSetAttribute(cv_g_kernel,
        cudaFuncAttributeMaxDynamicSharedMemorySize, smem_g);
    cudaFuncSetAttribute(cv_lrcost_kernel,
        cudaFuncAttributeMaxDynamicSharedMemorySize, smem_lr);

    cv_prep_kernel<<<dim3(HH, BB, 2), 448>>>(xl, xr);
    cv_g_kernel<<<dim3(2, HH, BB), 256, smem_g>>>(xl, xr);
    cv_lr_out_kernel<<<dim3(HH/4, DD, BB), 416>>>(out);
    cv_lrcost_kernel<<<dim3(4, HH, BB), 256, smem_lr>>>(xm, out);
}